// round 8
// baseline (speedup 1.0000x reference)
#include <cuda_runtime.h>
#include <cuda_fp16.h>
#include <math.h>

#define NN    32768
#define EE    262144
#define HID   64
#define HEADS 4
#define CC    64
#define HC    256
#define EDIM  3

// ---------------- scratch ----------------
// g_xh layout: per node, 32 colpairs x 4 heads x half2  => uint4 per colpair
__device__ __half  g_xh[(size_t)NN * HC];
__device__ float   g_as[NN * HEADS];
__device__ float   g_ad[NN * HEADS];
__device__ float   g_z[(size_t)NN * HID];
__device__ float   g_v[2 * EDIM * HEADS];
// CSR (built once per launch)
__device__ int     g_cnt[NN];        // histogram, then fill-cursor
__device__ int     g_rowptr[NN + 1];
__device__ int     g_csre[EE];       // edge id sorted by dst
__device__ int     g_csrs[EE];       // src node sorted by dst

// ---------------- f32x2 helpers ----------------
__device__ __forceinline__ unsigned long long splat2(float x) {
    unsigned long long r; unsigned u = __float_as_uint(x);
    asm("mov.b64 %0, {%1, %2};" : "=l"(r) : "r"(u), "r"(u));
    return r;
}
__device__ __forceinline__ void ffma2(unsigned long long& d, unsigned long long a, unsigned long long b) {
    asm("fma.rn.f32x2 %0, %1, %2, %3;" : "=l"(d) : "l"(a), "l"(b), "l"(d));
}
__device__ __forceinline__ void unpack2(unsigned long long v, float& lo, float& hi) {
    unsigned a, b;
    asm("mov.b64 {%0, %1}, %2;" : "=r"(a), "=r"(b) : "l"(v));
    lo = __uint_as_float(a); hi = __uint_as_float(b);
}
__device__ __forceinline__ unsigned long long pack2(float lo, float hi) {
    unsigned long long r;
    asm("mov.b64 %0, {%1, %2};" : "=l"(r) : "r"(__float_as_uint(lo)), "r"(__float_as_uint(hi)));
    return r;
}

// ---------------- init: zero histogram + compute g_v for both layers ----------------
__global__ void k_init(const float* __restrict__ We1, const float* __restrict__ ae1,
                       const float* __restrict__ We2, const float* __restrict__ ae2)
{
    int i = blockIdx.x * 256 + threadIdx.x;   // grid covers NN
    g_cnt[i] = 0;
    if (blockIdx.x == 0 && threadIdx.x < 2 * EDIM * HEADS) {
        int t = threadIdx.x;
        int L = t / (EDIM * HEADS);
        int r = t % (EDIM * HEADS);
        int d = r / HEADS, hh = r % HEADS;
        const float* We = L ? We2 : We1;
        const float* ae = L ? ae2 : ae1;
        float s = 0.f;
        for (int c = 0; c < CC; c++) s += We[d * HC + hh * CC + c] * ae[hh * CC + c];
        g_v[t] = s;
    }
}

// ---------------- CSR build ----------------
__global__ void k_hist(const int* __restrict__ dst) {
    int e = blockIdx.x * 256 + threadIdx.x;
    atomicAdd(&g_cnt[dst[e]], 1);
}

// single block, 1024 threads; each scans 32 counters
__global__ void __launch_bounds__(1024) k_scan() {
    __shared__ int wsum[32];
    int t = threadIdx.x, lane = t & 31, w = t >> 5;
    int base = t * 32;
    int loc[32];
    int s = 0;
    #pragma unroll
    for (int i = 0; i < 32; i++) { loc[i] = s; s += g_cnt[base + i]; }
    // warp inclusive scan of per-thread sums
    int v = s;
    #pragma unroll
    for (int off = 1; off < 32; off <<= 1) {
        int u = __shfl_up_sync(0xFFFFFFFFu, v, off);
        if (lane >= off) v += u;
    }
    if (lane == 31) wsum[w] = v;
    __syncthreads();
    if (w == 0) {
        int x = wsum[lane];
        #pragma unroll
        for (int off = 1; off < 32; off <<= 1) {
            int u = __shfl_up_sync(0xFFFFFFFFu, x, off);
            if (lane >= off) x += u;
        }
        wsum[lane] = x;
    }
    __syncthreads();
    int pre = (v - s) + (w > 0 ? wsum[w - 1] : 0);   // exclusive prefix for this thread
    #pragma unroll
    for (int i = 0; i < 32; i++) {
        int p = pre + loc[i];
        g_rowptr[base + i] = p;
        g_cnt[base + i]    = p;    // cursor for fill
    }
    if (t == 1023) g_rowptr[NN] = EE;
}

__global__ void k_fill(const int* __restrict__ src, const int* __restrict__ dst) {
    int e = blockIdx.x * 256 + threadIdx.x;
    int d = dst[e];
    int pos = atomicAdd(&g_cnt[d], 1);
    g_csre[pos] = e;
    g_csrs[pos] = src[e];
}

// ---------------- GEMM: x = z @ W (f32x2), fused alpha dots, fp16 transposed out ----------------
__global__ void __launch_bounds__(256, 2) k_gemm(
    const float* __restrict__ z, const float* __restrict__ W,
    const float* __restrict__ a_src, const float* __restrict__ a_dst)
{
    extern __shared__ float sm[];
    float* Ws = sm;               // 16384 floats
    float* zs = sm + HID * HC;    // 4096 floats
    int tid = threadIdx.x;
    int node0 = blockIdx.x * 64;

    {
        float4* d4 = (float4*)Ws;
        const float4* s4 = (const float4*)W;
        #pragma unroll
        for (int i = 0; i < 16; i++) d4[tid + i * 256] = s4[tid + i * 256];
        float4* z4 = (float4*)zs;
        const float4* zg4 = (const float4*)(z + (size_t)node0 * HID);
        #pragma unroll
        for (int i = 0; i < 4; i++) z4[tid + i * 256] = zg4[tid + i * 256];
    }
    __syncthreads();

    int w = tid >> 5, l = tid & 31;
    int nbase = node0 + w * 8;

    unsigned long long acc[8][4];
    #pragma unroll
    for (int i = 0; i < 8; i++)
        #pragma unroll
        for (int g = 0; g < 4; g++) acc[i][g] = 0ull;

    const unsigned long long* Ws8 = (const unsigned long long*)Ws;

    #pragma unroll 1
    for (int k0 = 0; k0 < HID; k0 += 4) {
        float4 zb[8];
        #pragma unroll
        for (int i = 0; i < 8; i++)
            zb[i] = ((const float4*)(zs + (w * 8 + i) * HID))[k0 >> 2];
        #pragma unroll
        for (int kk = 0; kk < 4; kk++) {
            unsigned long long w0 = Ws8[(k0 + kk) * 128 + l];
            unsigned long long w1 = Ws8[(k0 + kk) * 128 + 32 + l];
            unsigned long long w2 = Ws8[(k0 + kk) * 128 + 64 + l];
            unsigned long long w3 = Ws8[(k0 + kk) * 128 + 96 + l];
            #pragma unroll
            for (int i = 0; i < 8; i++) {
                float zk = (kk == 0) ? zb[i].x : (kk == 1) ? zb[i].y : (kk == 2) ? zb[i].z : zb[i].w;
                unsigned long long z2 = splat2(zk);
                ffma2(acc[i][0], z2, w0);
                ffma2(acc[i][1], z2, w1);
                ffma2(acc[i][2], z2, w2);
                ffma2(acc[i][3], z2, w3);
            }
        }
    }

    float2 asv[4], adv[4];
    #pragma unroll
    for (int g = 0; g < 4; g++) {
        asv[g] = ((const float2*)a_src)[g * 32 + l];
        adv[g] = ((const float2*)a_dst)[g * 32 + l];
    }

    #pragma unroll
    for (int i = 0; i < 8; i++) {
        int n = nbase + i;
        float ps[4], pd[4];
        unsigned xw[4];
        #pragma unroll
        for (int g = 0; g < 4; g++) {
            float f0, f1;
            unpack2(acc[i][g], f0, f1);
            __half2 h2 = __floats2half2_rn(f0, f1);
            xw[g] = *(unsigned*)&h2;
            ps[g] = f0 * asv[g].x + f1 * asv[g].y;
            pd[g] = f0 * adv[g].x + f1 * adv[g].y;
        }
        ((uint4*)(g_xh + (size_t)n * HC))[l] = make_uint4(xw[0], xw[1], xw[2], xw[3]);
        #pragma unroll
        for (int off = 16; off; off >>= 1) {
            #pragma unroll
            for (int g = 0; g < 4; g++) {
                ps[g] += __shfl_xor_sync(0xFFFFFFFFu, ps[g], off);
                pd[g] += __shfl_xor_sync(0xFFFFFFFFu, pd[g], off);
            }
        }
        if (l == 0) {
            ((float4*)g_as)[n] = make_float4(ps[0], ps[1], ps[2], ps[3]);
            ((float4*)g_ad)[n] = make_float4(pd[0], pd[1], pd[2], pd[3]);
        }
    }
}

// ---------------- fused aggregate: logits+exp+softmax+gather+LN+SiLU ----------------
// warp per destination node
__global__ void __launch_bounds__(256) k_agg(
    const float* __restrict__ ea, int L,
    const float* __restrict__ b, const float* __restrict__ lgm,
    const float* __restrict__ lbt, float* __restrict__ out)
{
    int n = (blockIdx.x * 256 + threadIdx.x) >> 5;
    int l = threadIdx.x & 31;
    const float* v = g_v + L * EDIM * HEADS;
    float4 adn = ((const float4*)g_ad)[n];
    int start = g_rowptr[n], end = g_rowptr[n + 1];

    unsigned long long ms0 = 0, ms1 = 0, ms2 = 0, ms3 = 0;
    float dn0 = 0.f, dn1 = 0.f, dn2 = 0.f, dn3 = 0.f;

    for (int c0 = start; c0 < end; c0 += 32) {
        int ne = min(32, end - c0);
        int s = 0;
        float ex0 = 0.f, ex1 = 0.f, ex2 = 0.f, ex3 = 0.f;
        if (l < ne) {
            int e = g_csre[c0 + l];
            s = g_csrs[c0 + l];
            float e0 = ea[3 * e], e1 = ea[3 * e + 1], e2 = ea[3 * e + 2];
            float4 as4 = ((const float4*)g_as)[s];
            float x0 = as4.x + adn.x + e0 * v[0] + e1 * v[4] + e2 * v[8];
            float x1 = as4.y + adn.y + e0 * v[1] + e1 * v[5] + e2 * v[9];
            float x2 = as4.z + adn.z + e0 * v[2] + e1 * v[6] + e2 * v[10];
            float x3 = as4.w + adn.w + e0 * v[3] + e1 * v[7] + e2 * v[11];
            x0 = (x0 > 0.f) ? x0 : 0.2f * x0;
            x1 = (x1 > 0.f) ? x1 : 0.2f * x1;
            x2 = (x2 > 0.f) ? x2 : 0.2f * x2;
            x3 = (x3 > 0.f) ? x3 : 0.2f * x3;
            ex0 = __expf(x0); ex1 = __expf(x1); ex2 = __expf(x2); ex3 = __expf(x3);
            dn0 += ex0; dn1 += ex1; dn2 += ex2; dn3 += ex3;
        }
        #pragma unroll 4
        for (int i = 0; i < ne; i++) {
            int si = __shfl_sync(0xFFFFFFFFu, s, i);
            float a0 = __shfl_sync(0xFFFFFFFFu, ex0, i);
            float a1 = __shfl_sync(0xFFFFFFFFu, ex1, i);
            float a2 = __shfl_sync(0xFFFFFFFFu, ex2, i);
            float a3 = __shfl_sync(0xFFFFFFFFu, ex3, i);
            uint4 xv = ((const uint4*)g_xh)[si * 32 + l];
            float2 f;
            f = __half22float2(*(__half2*)&xv.x); ffma2(ms0, splat2(a0), pack2(f.x, f.y));
            f = __half22float2(*(__half2*)&xv.y); ffma2(ms1, splat2(a1), pack2(f.x, f.y));
            f = __half22float2(*(__half2*)&xv.z); ffma2(ms2, splat2(a2), pack2(f.x, f.y));
            f = __half22float2(*(__half2*)&xv.w); ffma2(ms3, splat2(a3), pack2(f.x, f.y));
        }
    }

    // reduce denom partials across lanes
    #pragma unroll
    for (int off = 16; off; off >>= 1) {
        dn0 += __shfl_xor_sync(0xFFFFFFFFu, dn0, off);
        dn1 += __shfl_xor_sync(0xFFFFFFFFu, dn1, off);
        dn2 += __shfl_xor_sync(0xFFFFFFFFu, dn2, off);
        dn3 += __shfl_xor_sync(0xFFFFFFFFu, dn3, off);
    }
    float rd0 = 0.25f * __fdividef(1.f, dn0 + 1e-16f);
    float rd1 = 0.25f * __fdividef(1.f, dn1 + 1e-16f);
    float rd2 = 0.25f * __fdividef(1.f, dn2 + 1e-16f);
    float rd3 = 0.25f * __fdividef(1.f, dn3 + 1e-16f);

    unsigned long long accv = 0;
    ffma2(accv, splat2(rd0), ms0);
    ffma2(accv, splat2(rd1), ms1);
    ffma2(accv, splat2(rd2), ms2);
    ffma2(accv, splat2(rd3), ms3);
    float v0, v1;
    unpack2(accv, v0, v1);

    float2 b2 = ((const float2*)b)[l];
    v0 += b2.x; v1 += b2.y;

    // LayerNorm over 64 cols (lane owns cols 2l, 2l+1)
    float ssum = v0 + v1;
    #pragma unroll
    for (int off = 16; off; off >>= 1) ssum += __shfl_xor_sync(0xFFFFFFFFu, ssum, off);
    float mu = ssum * (1.0f / 64.0f);
    float q = (v0 - mu) * (v0 - mu) + (v1 - mu) * (v1 - mu);
    #pragma unroll
    for (int off = 16; off; off >>= 1) q += __shfl_xor_sync(0xFFFFFFFFu, q, off);
    float r = rsqrtf(q * (1.0f / 64.0f) + 1e-5f);
    float2 g2 = ((const float2*)lgm)[l];
    float2 t2 = ((const float2*)lbt)[l];
    float y0 = (v0 - mu) * r * g2.x + t2.x;
    float y1 = (v1 - mu) * r * g2.y + t2.y;
    y0 = y0 * __fdividef(1.0f, 1.0f + __expf(-y0));
    y1 = y1 * __fdividef(1.0f, 1.0f + __expf(-y1));
    ((float2*)(out + (size_t)n * 64))[l] = make_float2(y0, y1);
}

// ---------------- launch ----------------
extern "C" void kernel_launch(void* const* d_in, const int* in_sizes, int n_in,
                              void* d_out, int out_size)
{
    const float* h   = (const float*)d_in[1];
    const int*   ei  = (const int*)d_in[2];
    const float* ea  = (const float*)d_in[3];
    const int*   src = ei;
    const int*   dst = ei + EE;

    const float* W[2]   = { (const float*)d_in[4],  (const float*)d_in[12] };
    const float* We[2]  = { (const float*)d_in[5],  (const float*)d_in[13] };
    const float* asr[2] = { (const float*)d_in[6],  (const float*)d_in[14] };
    const float* ads[2] = { (const float*)d_in[7],  (const float*)d_in[15] };
    const float* aeg[2] = { (const float*)d_in[8],  (const float*)d_in[16] };
    const float* bb[2]  = { (const float*)d_in[9],  (const float*)d_in[17] };
    const float* lng[2] = { (const float*)d_in[10], (const float*)d_in[18] };
    const float* lnb[2] = { (const float*)d_in[11], (const float*)d_in[19] };

    const int smem = (HID * HC + 64 * HID) * (int)sizeof(float);  // 81920 B
    cudaFuncSetAttribute(k_gemm, cudaFuncAttributeMaxDynamicSharedMemorySize, smem);

    float* zbuf = nullptr;
    cudaGetSymbolAddress((void**)&zbuf, g_z);

    // CSR build (shared by both layers)
    k_init<<< NN / 256, 256 >>>(We[0], aeg[0], We[1], aeg[1]);
    k_hist<<< EE / 256, 256 >>>(dst);
    k_scan<<< 1, 1024 >>>();
    k_fill<<< EE / 256, 256 >>>(src, dst);

    const float* zin = h;
    for (int L = 0; L < 2; L++) {
        float* zout = (L == 0) ? zbuf : (float*)d_out;
        k_gemm<<< NN / 64, 256, smem >>>(zin, W[L], asr[L], ads[L]);
        k_agg <<< NN / 8, 256 >>>(ea, L, bb[L], lng[L], lnb[L], zout);
        zin = zbuf;
    }
}

// round 12
// speedup vs baseline: 1.4863x; 1.4863x over previous
#include <cuda_runtime.h>
#include <cuda_fp16.h>
#include <math.h>

#define NN    32768
#define EE    262144
#define HID   64
#define HEADS 4
#define CC    64
#define HC    256
#define EDIM  3

// ---------------- scratch ----------------
// g_xh layout: per node, 32 colpairs x 4 heads x half2  => uint4 per colpair
__device__ __half  g_xh[(size_t)NN * HC];
__device__ float   g_as[NN * HEADS];
__device__ float   g_ad[NN * HEADS];
__device__ float   g_ex[(size_t)EE * HEADS];   // exp(logit)
__device__ float   g_denom[NN * HEADS];
__device__ float   g_rdn[NN * HEADS];          // 0.25 / (denom + eps)
__device__ float   g_accum[(size_t)NN * CC];
__device__ float   g_z[(size_t)NN * HID];
__device__ float   g_v[2 * EDIM * HEADS];

// ---------------- f32x2 helpers ----------------
__device__ __forceinline__ unsigned long long splat2(float x) {
    unsigned long long r; unsigned u = __float_as_uint(x);
    asm("mov.b64 %0, {%1, %2};" : "=l"(r) : "r"(u), "r"(u));
    return r;
}
__device__ __forceinline__ void ffma2(unsigned long long& d, unsigned long long a, unsigned long long b) {
    asm("fma.rn.f32x2 %0, %1, %2, %3;" : "=l"(d) : "l"(a), "l"(b), "l"(d));
}
__device__ __forceinline__ void unpack2(unsigned long long v, float& lo, float& hi) {
    unsigned a, b;
    asm("mov.b64 {%0, %1}, %2;" : "=r"(a), "=r"(b) : "l"(v));
    lo = __uint_as_float(a); hi = __uint_as_float(b);
}
__device__ __forceinline__ unsigned long long pack2(float lo, float hi) {
    unsigned long long r;
    asm("mov.b64 %0, {%1, %2};" : "=l"(r) : "r"(__float_as_uint(lo)), "r"(__float_as_uint(hi)));
    return r;
}
__device__ __forceinline__ void red_v4(float* p, float a, float b, float c, float d) {
    asm volatile("red.global.add.v4.f32 [%0], {%1, %2, %3, %4};"
                 :: "l"(p), "f"(a), "f"(b), "f"(c), "f"(d) : "memory");
}

// ---------------- init: zero accumulators + compute g_v for both layers ----------------
__global__ void k_init(const float* __restrict__ We1, const float* __restrict__ ae1,
                       const float* __restrict__ We2, const float* __restrict__ ae2)
{
    int i = blockIdx.x * 256 + threadIdx.x;
    if (i < NN * HEADS) g_denom[i] = 0.0f;
    g_accum[i] = 0.0f;   // grid covers NN*CC
    if (blockIdx.x == 0 && threadIdx.x < 2 * EDIM * HEADS) {
        int t = threadIdx.x;
        int L = t / (EDIM * HEADS);
        int r = t % (EDIM * HEADS);
        int d = r / HEADS, hh = r % HEADS;
        const float* We = L ? We2 : We1;
        const float* ae = L ? ae2 : ae1;
        float s = 0.f;
        for (int c = 0; c < CC; c++) s += We[d * HC + hh * CC + c] * ae[hh * CC + c];
        g_v[t] = s;
    }
}

// ---------------- GEMM: x = z @ W (f32x2), fused alpha dots, fp16 transposed out ----------------
__global__ void __launch_bounds__(256, 2) k_gemm(
    const float* __restrict__ z, const float* __restrict__ W,
    const float* __restrict__ a_src, const float* __restrict__ a_dst)
{
    extern __shared__ float sm[];
    float* Ws = sm;               // 16384 floats
    float* zs = sm + HID * HC;    // 4096 floats
    int tid = threadIdx.x;
    int node0 = blockIdx.x * 64;

    {
        float4* d4 = (float4*)Ws;
        const float4* s4 = (const float4*)W;
        #pragma unroll
        for (int i = 0; i < 16; i++) d4[tid + i * 256] = s4[tid + i * 256];
        float4* z4 = (float4*)zs;
        const float4* zg4 = (const float4*)(z + (size_t)node0 * HID);
        #pragma unroll
        for (int i = 0; i < 4; i++) z4[tid + i * 256] = zg4[tid + i * 256];
    }
    __syncthreads();

    int w = tid >> 5, l = tid & 31;
    int nbase = node0 + w * 8;

    // lane l, head g: cols {64g+2l, 64g+2l+1}
    unsigned long long acc[8][4];
    #pragma unroll
    for (int i = 0; i < 8; i++)
        #pragma unroll
        for (int g = 0; g < 4; g++) acc[i][g] = 0ull;

    const unsigned long long* Ws8 = (const unsigned long long*)Ws;

    #pragma unroll 1
    for (int k0 = 0; k0 < HID; k0 += 4) {
        float4 zb[8];
        #pragma unroll
        for (int i = 0; i < 8; i++)
            zb[i] = ((const float4*)(zs + (w * 8 + i) * HID))[k0 >> 2];
        #pragma unroll
        for (int kk = 0; kk < 4; kk++) {
            unsigned long long w0 = Ws8[(k0 + kk) * 128 + l];
            unsigned long long w1 = Ws8[(k0 + kk) * 128 + 32 + l];
            unsigned long long w2 = Ws8[(k0 + kk) * 128 + 64 + l];
            unsigned long long w3 = Ws8[(k0 + kk) * 128 + 96 + l];
            #pragma unroll
            for (int i = 0; i < 8; i++) {
                float zk = (kk == 0) ? zb[i].x : (kk == 1) ? zb[i].y : (kk == 2) ? zb[i].z : zb[i].w;
                unsigned long long z2 = splat2(zk);
                ffma2(acc[i][0], z2, w0);
                ffma2(acc[i][1], z2, w1);
                ffma2(acc[i][2], z2, w2);
                ffma2(acc[i][3], z2, w3);
            }
        }
    }

    float2 asv[4], adv[4];
    #pragma unroll
    for (int g = 0; g < 4; g++) {
        asv[g] = ((const float2*)a_src)[g * 32 + l];
        adv[g] = ((const float2*)a_dst)[g * 32 + l];
    }

    #pragma unroll
    for (int i = 0; i < 8; i++) {
        int n = nbase + i;
        float ps[4], pd[4];
        unsigned xw[4];
        #pragma unroll
        for (int g = 0; g < 4; g++) {
            float f0, f1;
            unpack2(acc[i][g], f0, f1);
            __half2 h2 = __floats2half2_rn(f0, f1);
            xw[g] = *(unsigned*)&h2;
            ps[g] = f0 * asv[g].x + f1 * asv[g].y;
            pd[g] = f0 * adv[g].x + f1 * adv[g].y;
        }
        ((uint4*)(g_xh + (size_t)n * HC))[l] = make_uint4(xw[0], xw[1], xw[2], xw[3]);
        #pragma unroll
        for (int off = 16; off; off >>= 1) {
            #pragma unroll
            for (int g = 0; g < 4; g++) {
                ps[g] += __shfl_xor_sync(0xFFFFFFFFu, ps[g], off);
                pd[g] += __shfl_xor_sync(0xFFFFFFFFu, pd[g], off);
            }
        }
        if (l == 0) {
            ((float4*)g_as)[n] = make_float4(ps[0], ps[1], ps[2], ps[3]);
            ((float4*)g_ad)[n] = make_float4(pd[0], pd[1], pd[2], pd[3]);
        }
    }
}

// ---------------- fused edge pass: logit -> exp -> denom, 4 edges/thread ----------------
__global__ void __launch_bounds__(256) k_edge(
    const int* __restrict__ src, const int* __restrict__ dst,
    const float* __restrict__ ea, int L)
{
    int t = blockIdx.x * 256 + threadIdx.x;    // EE/4 threads
    const float* v = g_v + L * EDIM * HEADS;
    float vr[12];
    #pragma unroll
    for (int i = 0; i < 12; i++) vr[i] = v[i];

    int4 s4 = ((const int4*)src)[t];
    int4 d4 = ((const int4*)dst)[t];
    float4 ga = ((const float4*)ea)[t * 3 + 0];
    float4 gb = ((const float4*)ea)[t * 3 + 1];
    float4 gc = ((const float4*)ea)[t * 3 + 2];

    int ss[4] = { s4.x, s4.y, s4.z, s4.w };
    int dd[4] = { d4.x, d4.y, d4.z, d4.w };
    float e0[4] = { ga.x, ga.w, gb.z, gc.y };
    float e1[4] = { ga.y, gb.x, gb.w, gc.z };
    float e2[4] = { ga.z, gb.y, gc.x, gc.w };

    float4 as4[4], ad4[4];
    #pragma unroll
    for (int j = 0; j < 4; j++) {
        as4[j] = ((const float4*)g_as)[ss[j]];
        ad4[j] = ((const float4*)g_ad)[dd[j]];
    }

    #pragma unroll
    for (int j = 0; j < 4; j++) {
        float x0 = as4[j].x + ad4[j].x + e0[j] * vr[0] + e1[j] * vr[4] + e2[j] * vr[8];
        float x1 = as4[j].y + ad4[j].y + e0[j] * vr[1] + e1[j] * vr[5] + e2[j] * vr[9];
        float x2 = as4[j].z + ad4[j].z + e0[j] * vr[2] + e1[j] * vr[6] + e2[j] * vr[10];
        float x3 = as4[j].w + ad4[j].w + e0[j] * vr[3] + e1[j] * vr[7] + e2[j] * vr[11];
        x0 = (x0 > 0.f) ? x0 : 0.2f * x0;
        x1 = (x1 > 0.f) ? x1 : 0.2f * x1;
        x2 = (x2 > 0.f) ? x2 : 0.2f * x2;
        x3 = (x3 > 0.f) ? x3 : 0.2f * x3;
        float ex0 = __expf(x0), ex1 = __expf(x1), ex2 = __expf(x2), ex3 = __expf(x3);
        ((float4*)g_ex)[t * 4 + j] = make_float4(ex0, ex1, ex2, ex3);
        red_v4(&g_denom[dd[j] * 4], ex0, ex1, ex2, ex3);
    }
}

// ---------------- reciprocal denom, vectorized (head-mean 0.25 folded in) ----------------
__global__ void k_rcp() {
    int i = blockIdx.x * 256 + threadIdx.x;   // NN*HEADS/4 threads
    float4 dn = ((const float4*)g_denom)[i];
    float4 rd;
    rd.x = 0.25f * __fdividef(1.0f, dn.x + 1e-16f);
    rd.y = 0.25f * __fdividef(1.0f, dn.y + 1e-16f);
    rd.z = 0.25f * __fdividef(1.0f, dn.z + 1e-16f);
    rd.w = 0.25f * __fdividef(1.0f, dn.w + 1e-16f);
    ((float4*)g_rdn)[i] = rd;
    ((float4*)g_denom)[i] = make_float4(0.f, 0.f, 0.f, 0.f);   // ready for next layer
}

// ---------------- message: 2 edges/warp, 16 lanes/edge, red.v4 ----------------
// grid = EE/16 blocks of 256
__global__ void k_msg(const int* __restrict__ src, const int* __restrict__ dst) {
    int t = blockIdx.x * 256 + threadIdx.x;
    int lane = threadIdx.x & 31;
    int e = ((t >> 5) << 1) + (lane >> 4);    // 2 edges per warp
    int r = lane & 15;                        // lane within edge: cols 4r..4r+3
    int s = src[e], d = dst[e];
    float4 ex4 = ((const float4*)g_ex)[e];
    float4 rd4 = ((const float4*)g_rdn)[d];
    float al0 = ex4.x * rd4.x;
    float al1 = ex4.y * rd4.y;
    float al2 = ex4.z * rd4.z;
    float al3 = ex4.w * rd4.w;

    const uint4* xr = (const uint4*)(g_xh + (size_t)s * HC);
    uint4 a = xr[2 * r];       // colpair 2r : heads 0..3
    uint4 b = xr[2 * r + 1];   // colpair 2r+1

    unsigned long long A0 = splat2(al0), A1 = splat2(al1), A2 = splat2(al2), A3 = splat2(al3);

    float2 f; unsigned long long pa = 0ull, pb = 0ull;
    f = __half22float2(*(__half2*)&a.x); ffma2(pa, A0, pack2(f.x, f.y));
    f = __half22float2(*(__half2*)&a.y); ffma2(pa, A1, pack2(f.x, f.y));
    f = __half22float2(*(__half2*)&a.z); ffma2(pa, A2, pack2(f.x, f.y));
    f = __half22float2(*(__half2*)&a.w); ffma2(pa, A3, pack2(f.x, f.y));
    f = __half22float2(*(__half2*)&b.x); ffma2(pb, A0, pack2(f.x, f.y));
    f = __half22float2(*(__half2*)&b.y); ffma2(pb, A1, pack2(f.x, f.y));
    f = __half22float2(*(__half2*)&b.z); ffma2(pb, A2, pack2(f.x, f.y));
    f = __half22float2(*(__half2*)&b.w); ffma2(pb, A3, pack2(f.x, f.y));

    float m0, m1, m2, m3;
    unpack2(pa, m0, m1);
    unpack2(pb, m2, m3);
    red_v4(&g_accum[d * 64 + 4 * r], m0, m1, m2, m3);
}

// ---------------- bias + layernorm + silu + zero-for-next-layer ----------------
__global__ void k_fin(const float* __restrict__ b, const float* __restrict__ lg,
                      const float* __restrict__ lb, float* __restrict__ out)
{
    int n = (blockIdx.x * 256 + threadIdx.x) >> 5;
    int l = threadIdx.x & 31;
    if (n >= NN) return;
    float v0 = g_accum[n * 64 + l]      + b[l];
    float v1 = g_accum[n * 64 + 32 + l] + b[32 + l];
    g_accum[n * 64 + l]      = 0.0f;
    g_accum[n * 64 + 32 + l] = 0.0f;
    float s = v0 + v1;
    #pragma unroll
    for (int off = 16; off; off >>= 1) s += __shfl_xor_sync(0xFFFFFFFFu, s, off);
    float mu = s * (1.0f / 64.0f);
    float q = (v0 - mu) * (v0 - mu) + (v1 - mu) * (v1 - mu);
    #pragma unroll
    for (int off = 16; off; off >>= 1) q += __shfl_xor_sync(0xFFFFFFFFu, q, off);
    float r = rsqrtf(q * (1.0f / 64.0f) + 1e-5f);
    float y0 = (v0 - mu) * r * lg[l]      + lb[l];
    float y1 = (v1 - mu) * r * lg[32 + l] + lb[32 + l];
    y0 = y0 * __fdividef(1.0f, 1.0f + __expf(-y0));
    y1 = y1 * __fdividef(1.0f, 1.0f + __expf(-y1));
    out[n * 64 + l]      = y0;
    out[n * 64 + 32 + l] = y1;
}

// ---------------- launch ----------------
extern "C" void kernel_launch(void* const* d_in, const int* in_sizes, int n_in,
                              void* d_out, int out_size)
{
    const float* h   = (const float*)d_in[1];
    const int*   ei  = (const int*)d_in[2];
    const float* ea  = (const float*)d_in[3];
    const int*   src = ei;
    const int*   dst = ei + EE;

    const float* W[2]   = { (const float*)d_in[4],  (const float*)d_in[12] };
    const float* We[2]  = { (const float*)d_in[5],  (const float*)d_in[13] };
    const float* asr[2] = { (const float*)d_in[6],  (const float*)d_in[14] };
    const float* ads[2] = { (const float*)d_in[7],  (const float*)d_in[15] };
    const float* aeg[2] = { (const float*)d_in[8],  (const float*)d_in[16] };
    const float* bb[2]  = { (const float*)d_in[9],  (const float*)d_in[17] };
    const float* lng[2] = { (const float*)d_in[10], (const float*)d_in[18] };
    const float* lnb[2] = { (const float*)d_in[11], (const float*)d_in[19] };

    const int smem = (HID * HC + 64 * HID) * (int)sizeof(float);  // 81920 B
    cudaFuncSetAttribute(k_gemm, cudaFuncAttributeMaxDynamicSharedMemorySize, smem);

    float* zbuf = nullptr;
    cudaGetSymbolAddress((void**)&zbuf, g_z);

    k_init<<< NN * CC / 256, 256 >>>(We[0], aeg[0], We[1], aeg[1]);

    const float* zin = h;
    for (int L = 0; L < 2; L++) {
        float* zout = (L == 0) ? zbuf : (float*)d_out;
        k_gemm<<< NN / 64, 256, smem >>>(zin, W[L], asr[L], ads[L]);
        k_edge<<< EE / 1024, 256 >>>(src, dst, ea, L);
        k_rcp <<< NN * HEADS / 1024, 256 >>>();
        k_msg <<< EE / 16, 256 >>>(src, dst);
        k_fin <<< NN / 8, 256 >>>(bb[L], lng[L], lnb[L], zout);
        zin = zbuf;
    }
}